// round 3
// baseline (speedup 1.0000x reference)
#include <cuda_runtime.h>
#include <cuda_bf16.h>

#define THREADS 256

// Pair-reduce: lanes with (lane & s)==0 end with full reduction of `a`,
// lanes with (lane & s)!=0 end with full reduction of `b`.
__device__ __forceinline__ float pair_reduce(float a, float b, int s, int lane) {
    bool hi = (lane & s) != 0;
    float send = hi ? a : b;
    float recv = __shfl_xor_sync(0xffffffffu, send, s);
    float keep = hi ? b : a;
    return keep + recv;
}

__global__ __launch_bounds__(THREADS, 4) void snn_fused_kernel(
    const float* __restrict__ x,       // [B,T,A,D] = [2048,90,4,256]
    const float* __restrict__ w_ant,   // [4]
    const float* __restrict__ b_ant,   // scalar
    const float* __restrict__ w_hid,   // [10,256]
    const float* __restrict__ b_hid,   // [10]
    const float* __restrict__ w_time,  // [90]
    const float* __restrict__ b_time,  // scalar
    const float* __restrict__ w_out,   // [2,10]
    const float* __restrict__ b_out,   // [2]
    float* __restrict__ out)           // [B,2]
{
    __shared__ float4 s_whid4[10 * 64];    // w_hid as float4: [h][64]
    __shared__ float  s_snp[2][90][10];    // per-half partial sn_in
    __shared__ float  s_wtime[90];
    __shared__ float  s_bias[10];
    __shared__ float  s_fused[10];

    const int tid = threadIdx.x;
    const int b   = blockIdx.x;

    // ---- init: stage weights into smem ----
    const float4* wh4 = reinterpret_cast<const float4*>(w_hid);
    for (int i = tid; i < 640; i += THREADS) s_whid4[i] = wh4[i];
    if (tid < 90) s_wtime[tid] = w_time[tid];
    __syncthreads();
    if (tid < 10) {
        const float* row = reinterpret_cast<const float*>(&s_whid4[tid * 64]);
        float s = 0.f;
        #pragma unroll 8
        for (int d = 0; d < 256; ++d) s += row[d];
        s_bias[tid] = b_hid[tid] + b_ant[0] * s;   // fold conv bias into hidden bias
    }
    const float wa0 = w_ant[0], wa1 = w_ant[1], wa2 = w_ant[2], wa3 = w_ant[3];
    __syncthreads();

    const int warp = tid >> 5;
    const int lane = tid & 31;
    const int pair = warp >> 1;      // 0..3 : timestep group
    const int half = warp & 1;       // 0..1 : which 128-d half
    const int dbase = half * 32;     // float4 offset within an antenna row

    // per-batch base: 90*4*256 floats = 90*256 float4
    const float4* xb = reinterpret_cast<const float4*>(x) + (size_t)b * 90 * 256;

    // ---- phase 1: fused antenna-conv + hidden GEMV (half-d per warp) ----
    for (int t = pair; t < 90; t += 4) {
        const float4* xt = xb + t * 256 + dbase + lane;
        // 4 antennas, this warp's d-half: 4 independent loads (2KB/warp)
        float4 a0 = __ldcs(xt      );
        float4 a1 = __ldcs(xt + 64 );
        float4 a2 = __ldcs(xt + 128);
        float4 a3 = __ldcs(xt + 192);

        float4 f;
        f.x = fmaf(a3.x, wa3, fmaf(a2.x, wa2, fmaf(a1.x, wa1, a0.x * wa0)));
        f.y = fmaf(a3.y, wa3, fmaf(a2.y, wa2, fmaf(a1.y, wa1, a0.y * wa0)));
        f.z = fmaf(a3.z, wa3, fmaf(a2.z, wa2, fmaf(a1.z, wa1, a0.z * wa0)));
        f.w = fmaf(a3.w, wa3, fmaf(a2.w, wa2, fmaf(a1.w, wa1, a0.w * wa0)));

        float acc[10];
        #pragma unroll
        for (int h = 0; h < 10; ++h) {
            float4 w = s_whid4[h * 64 + dbase + lane];
            float r;
            r = f.x * w.x;
            r = fmaf(f.y, w.y, r);
            r = fmaf(f.z, w.z, r);
            r = fmaf(f.w, w.w, r);
            acc[h] = r;
        }

        // ---- log-packed warp reduction: 12 SHFL ----
        float v0 = pair_reduce(acc[0], acc[1], 16, lane);
        float v1 = pair_reduce(acc[2], acc[3], 16, lane);
        float v2 = pair_reduce(acc[4], acc[5], 16, lane);
        float v3 = pair_reduce(acc[6], acc[7], 16, lane);
        float v4 = pair_reduce(acc[8], acc[9], 16, lane);
        float u0 = pair_reduce(v0, v1, 8, lane);
        float u1 = pair_reduce(v2, v3, 8, lane);
        v4 += __shfl_xor_sync(0xffffffffu, v4, 8);
        float w0 = pair_reduce(u0, u1, 4, lane);
        v4 += __shfl_xor_sync(0xffffffffu, v4, 4);
        float z = pair_reduce(w0, v4, 2, lane);
        z += __shfl_xor_sync(0xffffffffu, z, 1);

        int h = (lane & 2) ? (8 + ((lane >> 4) & 1))
                           : (((lane >> 2) & 1) * 4 + ((lane >> 3) & 1) * 2 + ((lane >> 4) & 1));
        bool writer = ((lane & 1) == 0) && (((lane & 2) == 0) || ((lane & 12) == 0));
        if (writer) s_snp[half][t][h] = z;
    }
    __syncthreads();

    // ---- phase 2: Leaky scan over T (serial, 10 lanes) + time fuse ----
    if (tid < 10) {
        const int h = tid;
        const float bias = s_bias[h];
        float mem = 0.f, acc = 0.f;
        #pragma unroll 6
        for (int t = 0; t < 90; ++t) {
            float inp = s_snp[0][t][h] + s_snp[1][t][h] + bias;
            // reset from PREVIOUS mem, reset_mechanism='zero'
            float mem_new = (mem > 1.0f) ? 0.0f : fmaf(0.95f, mem, inp);
            if (mem_new > 1.0f) acc += s_wtime[t];   // spike: Heaviside(mem_new-1)
            mem = mem_new;
        }
        s_fused[h] = acc + b_time[0];
    }
    __syncthreads();

    // ---- phase 3: output GEMV + softmax (O=2) ----
    if (tid == 0) {
        float o0 = b_out[0], o1 = b_out[1];
        #pragma unroll
        for (int h = 0; h < 10; ++h) {
            o0 = fmaf(s_fused[h], w_out[h],      o0);
            o1 = fmaf(s_fused[h], w_out[10 + h], o1);
        }
        float m  = fmaxf(o0, o1);
        float e0 = __expf(o0 - m);
        float e1 = __expf(o1 - m);
        float inv = 1.0f / (e0 + e1);
        out[2 * b]     = e0 * inv;
        out[2 * b + 1] = e1 * inv;
    }
}

extern "C" void kernel_launch(void* const* d_in, const int* in_sizes, int n_in,
                              void* d_out, int out_size) {
    const float* x      = (const float*)d_in[0];
    const float* w_ant  = (const float*)d_in[1];
    const float* b_ant  = (const float*)d_in[2];
    const float* w_hid  = (const float*)d_in[3];
    const float* b_hid  = (const float*)d_in[4];
    const float* w_time = (const float*)d_in[5];
    const float* b_time = (const float*)d_in[6];
    const float* w_out  = (const float*)d_in[7];
    const float* b_out  = (const float*)d_in[8];
    float* out = (float*)d_out;

    const int B = in_sizes[0] / (90 * 4 * 256);   // 2048
    snn_fused_kernel<<<B, THREADS>>>(x, w_ant, b_ant, w_hid, b_hid,
                                     w_time, b_time, w_out, b_out, out);
}

// round 4
// speedup vs baseline: 1.0903x; 1.0903x over previous
#include <cuda_runtime.h>
#include <cuda_bf16.h>

#define THREADS 256
#define GRID_CAP 512

// Pair-reduce: lanes with (lane & s)==0 end with full reduction of `a`,
// lanes with (lane & s)!=0 end with full reduction of `b`.
__device__ __forceinline__ float pair_reduce(float a, float b, int s, int lane) {
    bool hi = (lane & s) != 0;
    float send = hi ? a : b;
    float recv = __shfl_xor_sync(0xffffffffu, send, s);
    float keep = hi ? b : a;
    return keep + recv;
}

__global__ __launch_bounds__(THREADS, 4) void snn_fused_kernel(
    const float* __restrict__ x,       // [B,T,A,D] = [B,90,4,256]
    const float* __restrict__ w_ant,   // [4]
    const float* __restrict__ b_ant,   // scalar
    const float* __restrict__ w_hid,   // [10,256]
    const float* __restrict__ b_hid,   // [10]
    const float* __restrict__ w_time,  // [90]
    const float* __restrict__ b_time,  // scalar
    const float* __restrict__ w_out,   // [2,10]
    const float* __restrict__ b_out,   // [2]
    float* __restrict__ out,           // [B,2]
    int B)
{
    __shared__ float4 s_whid4[10 * 64];   // w_hid as float4: [h][64]
    __shared__ float  s_sn[90][10];       // sn_in (pre-bias) per timestep
    __shared__ float  s_wtime[90];
    __shared__ float  s_bias[10];
    __shared__ float  s_fused[10];

    const int tid = threadIdx.x;

    // ---- one-time init: stage weights into smem ----
    const float4* wh4 = reinterpret_cast<const float4*>(w_hid);
    for (int i = tid; i < 640; i += THREADS) s_whid4[i] = wh4[i];
    if (tid < 90) s_wtime[tid] = w_time[tid];
    __syncthreads();
    if (tid < 10) {
        const float* row = reinterpret_cast<const float*>(&s_whid4[tid * 64]);
        float s = 0.f;
        #pragma unroll 8
        for (int d = 0; d < 256; ++d) s += row[d];
        s_bias[tid] = b_hid[tid] + b_ant[0] * s;   // fold conv bias into hidden bias
    }
    const float wa0 = w_ant[0], wa1 = w_ant[1], wa2 = w_ant[2], wa3 = w_ant[3];

    const int warp = tid >> 5;
    const int lane = tid & 31;

    // ---- persistent loop: each CTA handles B/grid batch rows ----
    for (int b = blockIdx.x; b < B; b += gridDim.x) {
        __syncthreads();   // s_sn reuse guard (and covers init on first pass)

        const float4* xb = reinterpret_cast<const float4*>(x) + (size_t)b * 90 * 256;

        // ---- phase 1: fused antenna-conv + hidden GEMV; one warp per t ----
        for (int t = warp; t < 90; t += 8) {
            const float4* xt = xb + t * 256 + lane;
            // antenna batch A: antennas 0,1, both d-halves
            float4 a00 = __ldcs(xt      );
            float4 a01 = __ldcs(xt + 32 );
            float4 a10 = __ldcs(xt + 64 );
            float4 a11 = __ldcs(xt + 96 );

            float4 f0, f1;   // partial fused over antennas {0,1}
            f0.x = fmaf(a10.x, wa1, a00.x * wa0);
            f0.y = fmaf(a10.y, wa1, a00.y * wa0);
            f0.z = fmaf(a10.z, wa1, a00.z * wa0);
            f0.w = fmaf(a10.w, wa1, a00.w * wa0);
            f1.x = fmaf(a11.x, wa1, a01.x * wa0);
            f1.y = fmaf(a11.y, wa1, a01.y * wa0);
            f1.z = fmaf(a11.z, wa1, a01.z * wa0);
            f1.w = fmaf(a11.w, wa1, a01.w * wa0);

            // antenna batch B loads: overlap with dot A
            float4 a20 = __ldcs(xt + 128);
            float4 a21 = __ldcs(xt + 160);
            float4 a30 = __ldcs(xt + 192);
            float4 a31 = __ldcs(xt + 224);

            float acc[10];
            #pragma unroll
            for (int h = 0; h < 10; ++h) {
                float4 w0 = s_whid4[h * 64 + lane];
                float4 w1 = s_whid4[h * 64 + lane + 32];
                float r;
                r = f0.x * w0.x;
                r = fmaf(f0.y, w0.y, r);
                r = fmaf(f0.z, w0.z, r);
                r = fmaf(f0.w, w0.w, r);
                r = fmaf(f1.x, w1.x, r);
                r = fmaf(f1.y, w1.y, r);
                r = fmaf(f1.z, w1.z, r);
                r = fmaf(f1.w, w1.w, r);
                acc[h] = r;
            }

            // partial fused over antennas {2,3}; accumulate into same dots
            f0.x = fmaf(a30.x, wa3, a20.x * wa2);
            f0.y = fmaf(a30.y, wa3, a20.y * wa2);
            f0.z = fmaf(a30.z, wa3, a20.z * wa2);
            f0.w = fmaf(a30.w, wa3, a20.w * wa2);
            f1.x = fmaf(a31.x, wa3, a21.x * wa2);
            f1.y = fmaf(a31.y, wa3, a21.y * wa2);
            f1.z = fmaf(a31.z, wa3, a21.z * wa2);
            f1.w = fmaf(a31.w, wa3, a21.w * wa2);

            #pragma unroll
            for (int h = 0; h < 10; ++h) {
                float4 w0 = s_whid4[h * 64 + lane];
                float4 w1 = s_whid4[h * 64 + lane + 32];
                float r = acc[h];
                r = fmaf(f0.x, w0.x, r);
                r = fmaf(f0.y, w0.y, r);
                r = fmaf(f0.z, w0.z, r);
                r = fmaf(f0.w, w0.w, r);
                r = fmaf(f1.x, w1.x, r);
                r = fmaf(f1.y, w1.y, r);
                r = fmaf(f1.z, w1.z, r);
                r = fmaf(f1.w, w1.w, r);
                acc[h] = r;
            }

            // ---- log-packed warp reduction: 12 SHFL total ----
            float v0 = pair_reduce(acc[0], acc[1], 16, lane);
            float v1 = pair_reduce(acc[2], acc[3], 16, lane);
            float v2 = pair_reduce(acc[4], acc[5], 16, lane);
            float v3 = pair_reduce(acc[6], acc[7], 16, lane);
            float v4 = pair_reduce(acc[8], acc[9], 16, lane);
            float u0 = pair_reduce(v0, v1, 8, lane);
            float u1 = pair_reduce(v2, v3, 8, lane);
            v4 += __shfl_xor_sync(0xffffffffu, v4, 8);
            float w0r = pair_reduce(u0, u1, 4, lane);
            v4 += __shfl_xor_sync(0xffffffffu, v4, 4);
            float z = pair_reduce(w0r, v4, 2, lane);
            z += __shfl_xor_sync(0xffffffffu, z, 1);

            int h = (lane & 2) ? (8 + ((lane >> 4) & 1))
                               : (((lane >> 2) & 1) * 4 + ((lane >> 3) & 1) * 2 + ((lane >> 4) & 1));
            bool writer = ((lane & 1) == 0) && (((lane & 2) == 0) || ((lane & 12) == 0));
            if (writer) s_sn[t][h] = z;
        }
        __syncthreads();

        // ---- phase 2: Leaky scan over T (serial, 10 lanes) + time fuse ----
        if (tid < 10) {
            const int h = tid;
            const float bias = s_bias[h];
            float mem = 0.f, acc = 0.f;
            #pragma unroll 6
            for (int t = 0; t < 90; ++t) {
                float inp = s_sn[t][h] + bias;
                // reset from PREVIOUS mem, reset_mechanism='zero'
                float mem_new = (mem > 1.0f) ? 0.0f : fmaf(0.95f, mem, inp);
                if (mem_new > 1.0f) acc += s_wtime[t];   // spike
                mem = mem_new;
            }
            s_fused[h] = acc + b_time[0];
        }
        __syncthreads();

        // ---- phase 3: output GEMV + softmax (O=2) ----
        if (tid == 0) {
            float o0 = b_out[0], o1 = b_out[1];
            #pragma unroll
            for (int h = 0; h < 10; ++h) {
                o0 = fmaf(s_fused[h], w_out[h],      o0);
                o1 = fmaf(s_fused[h], w_out[10 + h], o1);
            }
            float m  = fmaxf(o0, o1);
            float e0 = __expf(o0 - m);
            float e1 = __expf(o1 - m);
            float inv = 1.0f / (e0 + e1);
            out[2 * b]     = e0 * inv;
            out[2 * b + 1] = e1 * inv;
        }
    }
}

extern "C" void kernel_launch(void* const* d_in, const int* in_sizes, int n_in,
                              void* d_out, int out_size) {
    const float* x      = (const float*)d_in[0];
    const float* w_ant  = (const float*)d_in[1];
    const float* b_ant  = (const float*)d_in[2];
    const float* w_hid  = (const float*)d_in[3];
    const float* b_hid  = (const float*)d_in[4];
    const float* w_time = (const float*)d_in[5];
    const float* b_time = (const float*)d_in[6];
    const float* w_out  = (const float*)d_in[7];
    const float* b_out  = (const float*)d_in[8];
    float* out = (float*)d_out;

    const int B = in_sizes[0] / (90 * 4 * 256);   // 2048
    const int grid = (B < GRID_CAP) ? B : GRID_CAP;
    snn_fused_kernel<<<grid, THREADS>>>(x, w_ant, b_ant, w_hid, b_hid,
                                        w_time, b_time, w_out, b_out, out, B);
}

// round 5
// speedup vs baseline: 1.1667x; 1.0700x over previous
#include <cuda_runtime.h>
#include <cuda_bf16.h>

#define THREADS 256
#define GRID_CAP 512

// Pair-reduce: lanes with (lane & s)==0 end with full reduction of `a`,
// lanes with (lane & s)!=0 end with full reduction of `b`.
__device__ __forceinline__ float pair_reduce(float a, float b, int s, int lane) {
    bool hi = (lane & s) != 0;
    float send = hi ? a : b;
    float recv = __shfl_xor_sync(0xffffffffu, send, s);
    float keep = hi ? b : a;
    return keep + recv;
}

__global__ __launch_bounds__(THREADS, 4) void snn_fused_kernel(
    const float* __restrict__ x,       // [B,T,A,D] = [B,90,4,256]
    const float* __restrict__ w_ant,   // [4]
    const float* __restrict__ b_ant,   // scalar
    const float* __restrict__ w_hid,   // [10,256]
    const float* __restrict__ b_hid,   // [10]
    const float* __restrict__ w_time,  // [90]
    const float* __restrict__ b_time,  // scalar
    const float* __restrict__ w_out,   // [2,10]
    const float* __restrict__ b_out,   // [2]
    float* __restrict__ out,           // [B,2]
    int B)
{
    __shared__ float4 s_whid4[10 * 64];    // w_hid as float4: [h][64]
    __shared__ float  s_sn[2][90][10];     // double-buffered sn_in
    __shared__ float  s_wtime[90];
    __shared__ float  s_bias[10];

    const int tid  = threadIdx.x;
    const int warp = tid >> 5;
    const int lane = tid & 31;

    // ---- one-time init: stage weights into smem ----
    const float4* wh4 = reinterpret_cast<const float4*>(w_hid);
    for (int i = tid; i < 640; i += THREADS) s_whid4[i] = wh4[i];
    if (tid < 90) s_wtime[tid] = w_time[tid];
    __syncthreads();
    if (tid < 10) {
        const float* row = reinterpret_cast<const float*>(&s_whid4[tid * 64]);
        float s = 0.f;
        #pragma unroll 8
        for (int d = 0; d < 256; ++d) s += row[d];
        s_bias[tid] = b_hid[tid] + b_ant[0] * s;   // fold conv bias into hidden bias
    }
    const float wa0 = w_ant[0], wa1 = w_ant[1], wa2 = w_ant[2], wa3 = w_ant[3];
    __syncthreads();

    // scan + output for one row, executed by warp 7 (lanes < 10 active in scan)
    auto scan_row = [&](int b, int buf) {
        float fused = 0.f;
        if (lane < 10) {
            const int h = lane;
            const float bias = s_bias[h];
            float mem = 0.f, acc = 0.f;
            #pragma unroll 6
            for (int t = 0; t < 90; ++t) {
                float inp = s_sn[buf][t][h] + bias;
                // reset from PREVIOUS mem, reset_mechanism='zero'
                float mem_new = (mem > 1.0f) ? 0.0f : fmaf(0.95f, mem, inp);
                if (mem_new > 1.0f) acc += s_wtime[t];   // spike
                mem = mem_new;
            }
            fused = acc + b_time[0];
        }
        // per-lane contribution to the two logits, reduce over warp
        float c0 = (lane < 10) ? fused * __ldg(w_out + lane)      : 0.f;
        float c1 = (lane < 10) ? fused * __ldg(w_out + 10 + lane) : 0.f;
        #pragma unroll
        for (int s = 16; s > 0; s >>= 1) {
            c0 += __shfl_xor_sync(0xffffffffu, c0, s);
            c1 += __shfl_xor_sync(0xffffffffu, c1, s);
        }
        if (lane == 0) {
            float o0 = c0 + b_out[0];
            float o1 = c1 + b_out[1];
            float m  = fmaxf(o0, o1);
            float e0 = __expf(o0 - m);
            float e1 = __expf(o1 - m);
            float inv = 1.0f / (e0 + e1);
            out[2 * b]     = e0 * inv;
            out[2 * b + 1] = e1 * inv;
        }
    };

    // ---- persistent loop: warps 0-6 produce sn, warp 7 scans previous row ----
    int iter = 0;
    int b;
    for (b = blockIdx.x; b < B; b += gridDim.x, ++iter) {
        const int buf = iter & 1;

        if (warp < 7) {
            const float4* xb = reinterpret_cast<const float4*>(x) + (size_t)b * 90 * 256;
            for (int t = warp; t < 90; t += 7) {
                const float4* xt = xb + t * 256 + lane;
                // antenna batch A: antennas 0,1
                float4 a00 = __ldcs(xt      );
                float4 a01 = __ldcs(xt + 32 );
                float4 a10 = __ldcs(xt + 64 );
                float4 a11 = __ldcs(xt + 96 );

                float4 f0, f1;
                f0.x = fmaf(a10.x, wa1, a00.x * wa0);
                f0.y = fmaf(a10.y, wa1, a00.y * wa0);
                f0.z = fmaf(a10.z, wa1, a00.z * wa0);
                f0.w = fmaf(a10.w, wa1, a00.w * wa0);
                f1.x = fmaf(a11.x, wa1, a01.x * wa0);
                f1.y = fmaf(a11.y, wa1, a01.y * wa0);
                f1.z = fmaf(a11.z, wa1, a01.z * wa0);
                f1.w = fmaf(a11.w, wa1, a01.w * wa0);

                // antenna batch B loads overlap with dot A
                float4 a20 = __ldcs(xt + 128);
                float4 a21 = __ldcs(xt + 160);
                float4 a30 = __ldcs(xt + 192);
                float4 a31 = __ldcs(xt + 224);

                float acc[10];
                #pragma unroll
                for (int h = 0; h < 10; ++h) {
                    float4 w0 = s_whid4[h * 64 + lane];
                    float4 w1 = s_whid4[h * 64 + lane + 32];
                    float r;
                    r = f0.x * w0.x;
                    r = fmaf(f0.y, w0.y, r);
                    r = fmaf(f0.z, w0.z, r);
                    r = fmaf(f0.w, w0.w, r);
                    r = fmaf(f1.x, w1.x, r);
                    r = fmaf(f1.y, w1.y, r);
                    r = fmaf(f1.z, w1.z, r);
                    r = fmaf(f1.w, w1.w, r);
                    acc[h] = r;
                }

                f0.x = fmaf(a30.x, wa3, a20.x * wa2);
                f0.y = fmaf(a30.y, wa3, a20.y * wa2);
                f0.z = fmaf(a30.z, wa3, a20.z * wa2);
                f0.w = fmaf(a30.w, wa3, a20.w * wa2);
                f1.x = fmaf(a31.x, wa3, a21.x * wa2);
                f1.y = fmaf(a31.y, wa3, a21.y * wa2);
                f1.z = fmaf(a31.z, wa3, a21.z * wa2);
                f1.w = fmaf(a31.w, wa3, a21.w * wa2);

                #pragma unroll
                for (int h = 0; h < 10; ++h) {
                    float4 w0 = s_whid4[h * 64 + lane];
                    float4 w1 = s_whid4[h * 64 + lane + 32];
                    float r = acc[h];
                    r = fmaf(f0.x, w0.x, r);
                    r = fmaf(f0.y, w0.y, r);
                    r = fmaf(f0.z, w0.z, r);
                    r = fmaf(f0.w, w0.w, r);
                    r = fmaf(f1.x, w1.x, r);
                    r = fmaf(f1.y, w1.y, r);
                    r = fmaf(f1.z, w1.z, r);
                    r = fmaf(f1.w, w1.w, r);
                    acc[h] = r;
                }

                // ---- log-packed warp reduction: 12 SHFL ----
                float v0 = pair_reduce(acc[0], acc[1], 16, lane);
                float v1 = pair_reduce(acc[2], acc[3], 16, lane);
                float v2 = pair_reduce(acc[4], acc[5], 16, lane);
                float v3 = pair_reduce(acc[6], acc[7], 16, lane);
                float v4 = pair_reduce(acc[8], acc[9], 16, lane);
                float u0 = pair_reduce(v0, v1, 8, lane);
                float u1 = pair_reduce(v2, v3, 8, lane);
                v4 += __shfl_xor_sync(0xffffffffu, v4, 8);
                float w0r = pair_reduce(u0, u1, 4, lane);
                v4 += __shfl_xor_sync(0xffffffffu, v4, 4);
                float z = pair_reduce(w0r, v4, 2, lane);
                z += __shfl_xor_sync(0xffffffffu, z, 1);

                int h = (lane & 2) ? (8 + ((lane >> 4) & 1))
                                   : (((lane >> 2) & 1) * 4 + ((lane >> 3) & 1) * 2 + ((lane >> 4) & 1));
                bool writer = ((lane & 1) == 0) && (((lane & 2) == 0) || ((lane & 12) == 0));
                if (writer) s_sn[buf][t][h] = z;
            }
        } else {
            // warp 7: scan the previous row (produced last iteration)
            if (iter > 0) scan_row(b - gridDim.x, buf ^ 1);
        }
        __syncthreads();
    }

    // ---- epilogue: scan the final row ----
    if (iter > 0 && warp == 7) {
        scan_row(b - gridDim.x, (iter - 1) & 1);
    }
}

extern "C" void kernel_launch(void* const* d_in, const int* in_sizes, int n_in,
                              void* d_out, int out_size) {
    const float* x      = (const float*)d_in[0];
    const float* w_ant  = (const float*)d_in[1];
    const float* b_ant  = (const float*)d_in[2];
    const float* w_hid  = (const float*)d_in[3];
    const float* b_hid  = (const float*)d_in[4];
    const float* w_time = (const float*)d_in[5];
    const float* b_time = (const float*)d_in[6];
    const float* w_out  = (const float*)d_in[7];
    const float* b_out  = (const float*)d_in[8];
    float* out = (float*)d_out;

    const int B = in_sizes[0] / (90 * 4 * 256);   // 2048
    const int grid = (B < GRID_CAP) ? B : GRID_CAP;
    snn_fused_kernel<<<grid, THREADS>>>(x, w_ant, b_ant, w_hid, b_hid,
                                        w_time, b_time, w_out, b_out, out, B);
}

// round 6
// speedup vs baseline: 1.2301x; 1.0544x over previous
#include <cuda_runtime.h>
#include <cuda_bf16.h>

#define THREADS 256

// Pair-reduce: lanes with (lane & s)==0 end with full reduction of `a`,
// lanes with (lane & s)!=0 end with full reduction of `b`.
__device__ __forceinline__ float pair_reduce(float a, float b, int s, int lane) {
    bool hi = (lane & s) != 0;
    float send = hi ? a : b;
    float recv = __shfl_xor_sync(0xffffffffu, send, s);
    float keep = hi ? b : a;
    return keep + recv;
}

__global__ __launch_bounds__(THREADS, 5) void snn_fused_kernel(
    const float* __restrict__ x,       // [B,T,A,D] = [B,90,4,256]
    const float* __restrict__ w_ant,   // [4]
    const float* __restrict__ b_ant,   // scalar
    const float* __restrict__ w_hid,   // [10,256]
    const float* __restrict__ b_hid,   // [10]
    const float* __restrict__ w_time,  // [90]
    const float* __restrict__ b_time,  // scalar
    const float* __restrict__ w_out,   // [2,10]
    const float* __restrict__ b_out,   // [2]
    float* __restrict__ out,           // [B,2]
    int B)
{
    __shared__ float4 s_whid4[10 * 64];    // w_hid as float4: [h][64]
    __shared__ float  s_sn[2][90][10];     // double-buffered sn_in
    __shared__ float  s_wtime[90];
    __shared__ float  s_bias[10];

    const int tid  = threadIdx.x;
    const int warp = tid >> 5;
    const int lane = tid & 31;

    // ---- one-time init: stage weights into smem ----
    const float4* wh4 = reinterpret_cast<const float4*>(w_hid);
    for (int i = tid; i < 640; i += THREADS) s_whid4[i] = wh4[i];
    if (tid < 90) s_wtime[tid] = w_time[tid];
    __syncthreads();
    if (tid < 10) {
        const float* row = reinterpret_cast<const float*>(&s_whid4[tid * 64]);
        float s = 0.f;
        #pragma unroll 8
        for (int d = 0; d < 256; ++d) s += row[d];
        s_bias[tid] = b_hid[tid] + b_ant[0] * s;   // fold conv bias into hidden bias
    }
    const float wa0 = w_ant[0], wa1 = w_ant[1], wa2 = w_ant[2], wa3 = w_ant[3];
    __syncthreads();

    // scan + output for one row, executed by warp 7 (lanes < 10 active in scan)
    auto scan_row = [&](int b, int buf) {
        float fused = 0.f;
        if (lane < 10) {
            const int h = lane;
            const float bias = s_bias[h];
            float mem = 0.f, acc = 0.f;
            #pragma unroll 6
            for (int t = 0; t < 90; ++t) {
                float inp = s_sn[buf][t][h] + bias;
                // reset from PREVIOUS mem, reset_mechanism='zero'
                float mem_new = (mem > 1.0f) ? 0.0f : fmaf(0.95f, mem, inp);
                if (mem_new > 1.0f) acc += s_wtime[t];   // spike
                mem = mem_new;
            }
            fused = acc + b_time[0];
        }
        // per-lane contribution to the two logits, reduce over warp
        float c0 = (lane < 10) ? fused * __ldg(w_out + lane)      : 0.f;
        float c1 = (lane < 10) ? fused * __ldg(w_out + 10 + lane) : 0.f;
        #pragma unroll
        for (int s = 16; s > 0; s >>= 1) {
            c0 += __shfl_xor_sync(0xffffffffu, c0, s);
            c1 += __shfl_xor_sync(0xffffffffu, c1, s);
        }
        if (lane == 0) {
            float o0 = c0 + b_out[0];
            float o1 = c1 + b_out[1];
            float m  = fmaxf(o0, o1);
            float e0 = __expf(o0 - m);
            float e1 = __expf(o1 - m);
            float inv = 1.0f / (e0 + e1);
            out[2 * b]     = e0 * inv;
            out[2 * b + 1] = e1 * inv;
        }
    };

    // ---- persistent loop: warps 0-6 produce sn, warp 7 scans previous row ----
    int iter = 0;
    int b;
    for (b = blockIdx.x; b < B; b += gridDim.x, ++iter) {
        const int buf = iter & 1;

        if (warp < 7) {
            const float4* xb = reinterpret_cast<const float4*>(x) + (size_t)b * 90 * 256;
            for (int t = warp; t < 90; t += 7) {
                const float4* xt = xb + t * 256 + lane;
                float acc[10];

                // ---- half 0: all 4 antennas, d-offset 0 ----
                {
                    float4 a0 = __ldcs(xt      );
                    float4 a1 = __ldcs(xt + 64 );
                    float4 a2 = __ldcs(xt + 128);
                    float4 a3 = __ldcs(xt + 192);
                    float4 f;
                    f.x = fmaf(a3.x, wa3, fmaf(a2.x, wa2, fmaf(a1.x, wa1, a0.x * wa0)));
                    f.y = fmaf(a3.y, wa3, fmaf(a2.y, wa2, fmaf(a1.y, wa1, a0.y * wa0)));
                    f.z = fmaf(a3.z, wa3, fmaf(a2.z, wa2, fmaf(a1.z, wa1, a0.z * wa0)));
                    f.w = fmaf(a3.w, wa3, fmaf(a2.w, wa2, fmaf(a1.w, wa1, a0.w * wa0)));
                    #pragma unroll
                    for (int h = 0; h < 10; ++h) {
                        float4 w = s_whid4[h * 64 + lane];
                        float r;
                        r = f.x * w.x;
                        r = fmaf(f.y, w.y, r);
                        r = fmaf(f.z, w.z, r);
                        r = fmaf(f.w, w.w, r);
                        acc[h] = r;
                    }
                }

                // ---- half 1: all 4 antennas, d-offset 32 (float4 units) ----
                {
                    float4 a0 = __ldcs(xt + 32 );
                    float4 a1 = __ldcs(xt + 96 );
                    float4 a2 = __ldcs(xt + 160);
                    float4 a3 = __ldcs(xt + 224);
                    float4 f;
                    f.x = fmaf(a3.x, wa3, fmaf(a2.x, wa2, fmaf(a1.x, wa1, a0.x * wa0)));
                    f.y = fmaf(a3.y, wa3, fmaf(a2.y, wa2, fmaf(a1.y, wa1, a0.y * wa0)));
                    f.z = fmaf(a3.z, wa3, fmaf(a2.z, wa2, fmaf(a1.z, wa1, a0.z * wa0)));
                    f.w = fmaf(a3.w, wa3, fmaf(a2.w, wa2, fmaf(a1.w, wa1, a0.w * wa0)));
                    #pragma unroll
                    for (int h = 0; h < 10; ++h) {
                        float4 w = s_whid4[h * 64 + lane + 32];
                        float r = acc[h];
                        r = fmaf(f.x, w.x, r);
                        r = fmaf(f.y, w.y, r);
                        r = fmaf(f.z, w.z, r);
                        r = fmaf(f.w, w.w, r);
                        acc[h] = r;
                    }
                }

                // ---- log-packed warp reduction: 12 SHFL ----
                float v0 = pair_reduce(acc[0], acc[1], 16, lane);
                float v1 = pair_reduce(acc[2], acc[3], 16, lane);
                float v2 = pair_reduce(acc[4], acc[5], 16, lane);
                float v3 = pair_reduce(acc[6], acc[7], 16, lane);
                float v4 = pair_reduce(acc[8], acc[9], 16, lane);
                float u0 = pair_reduce(v0, v1, 8, lane);
                float u1 = pair_reduce(v2, v3, 8, lane);
                v4 += __shfl_xor_sync(0xffffffffu, v4, 8);
                float w0r = pair_reduce(u0, u1, 4, lane);
                v4 += __shfl_xor_sync(0xffffffffu, v4, 4);
                float z = pair_reduce(w0r, v4, 2, lane);
                z += __shfl_xor_sync(0xffffffffu, z, 1);

                int h = (lane & 2) ? (8 + ((lane >> 4) & 1))
                                   : (((lane >> 2) & 1) * 4 + ((lane >> 3) & 1) * 2 + ((lane >> 4) & 1));
                bool writer = ((lane & 1) == 0) && (((lane & 2) == 0) || ((lane & 12) == 0));
                if (writer) s_sn[buf][t][h] = z;
            }
        } else {
            // warp 7: scan the previous row (produced last iteration)
            if (iter > 0) scan_row(b - gridDim.x, buf ^ 1);
        }
        __syncthreads();
    }

    // ---- epilogue: scan the final row ----
    if (iter > 0 && warp == 7) {
        scan_row(b - gridDim.x, (iter - 1) & 1);
    }
}

extern "C" void kernel_launch(void* const* d_in, const int* in_sizes, int n_in,
                              void* d_out, int out_size) {
    const float* x      = (const float*)d_in[0];
    const float* w_ant  = (const float*)d_in[1];
    const float* b_ant  = (const float*)d_in[2];
    const float* w_hid  = (const float*)d_in[3];
    const float* b_hid  = (const float*)d_in[4];
    const float* w_time = (const float*)d_in[5];
    const float* b_time = (const float*)d_in[6];
    const float* w_out  = (const float*)d_in[7];
    const float* b_out  = (const float*)d_in[8];
    float* out = (float*)d_out;

    const int B = in_sizes[0] / (90 * 4 * 256);   // 2048
    // occupancy capacity = 148 SMs * 5 CTAs = 740. Pick grid so every CTA
    // does ceil(B/740) rows -> balanced, near-full slot fill.
    const int rows_per = (B + 739) / 740;                 // 3 for B=2048
    int grid = (B + rows_per - 1) / rows_per;             // 683
    if (grid > B) grid = B;
    snn_fused_kernel<<<grid, THREADS>>>(x, w_ant, b_ant, w_hid, b_hid,
                                        w_time, b_time, w_out, b_out, out, B);
}

// round 7
// speedup vs baseline: 1.2330x; 1.0023x over previous
#include <cuda_runtime.h>
#include <cuda_bf16.h>

#define THREADS 256

// Pair-reduce: lanes with (lane & s)==0 end with full reduction of `a`,
// lanes with (lane & s)!=0 end with full reduction of `b`.
__device__ __forceinline__ float pair_reduce(float a, float b, int s, int lane) {
    bool hi = (lane & s) != 0;
    float send = hi ? a : b;
    float recv = __shfl_xor_sync(0xffffffffu, send, s);
    float keep = hi ? b : a;
    return keep + recv;
}

__global__ __launch_bounds__(THREADS, 6) void snn_fused_kernel(
    const float* __restrict__ x,       // [B,T,A,D] = [B,90,4,256]
    const float* __restrict__ w_ant,   // [4]
    const float* __restrict__ b_ant,   // scalar
    const float* __restrict__ w_hid,   // [10,256]
    const float* __restrict__ b_hid,   // [10]
    const float* __restrict__ w_time,  // [90]
    const float* __restrict__ b_time,  // scalar
    const float* __restrict__ w_out,   // [2,10]
    const float* __restrict__ b_out,   // [2]
    float* __restrict__ out,           // [B,2]
    int B)
{
    __shared__ float4 s_whid4[10 * 64];    // w_hid as float4: [h][64]
    __shared__ float  s_sn[2][90][10];     // double-buffered sn_in
    __shared__ float  s_wtime[90];
    __shared__ float  s_bias[10];

    const int tid  = threadIdx.x;
    const int warp = tid >> 5;
    const int lane = tid & 31;

    // ---- one-time init: stage weights into smem ----
    const float4* wh4 = reinterpret_cast<const float4*>(w_hid);
    for (int i = tid; i < 640; i += THREADS) s_whid4[i] = wh4[i];
    if (tid < 90) s_wtime[tid] = w_time[tid];
    __syncthreads();
    if (tid < 10) {
        const float* row = reinterpret_cast<const float*>(&s_whid4[tid * 64]);
        float s = 0.f;
        #pragma unroll 8
        for (int d = 0; d < 256; ++d) s += row[d];
        s_bias[tid] = b_hid[tid] + b_ant[0] * s;   // fold conv bias into hidden bias
    }
    const float wa0 = w_ant[0], wa1 = w_ant[1], wa2 = w_ant[2], wa3 = w_ant[3];
    __syncthreads();

    // loop-invariant per-lane reduction metadata (hoisted out of t-loop)
    const int h_mine = (lane & 2) ? (8 + ((lane >> 4) & 1))
                                  : (((lane >> 2) & 1) * 4 + ((lane >> 3) & 1) * 2 + ((lane >> 4) & 1));
    const bool writer = ((lane & 1) == 0) && (((lane & 2) == 0) || ((lane & 12) == 0));
    // per-lane weight row bases (float4 units)
    const float4* wl0 = s_whid4 + lane;
    const float4* wl1 = s_whid4 + lane + 32;

    // scan + output for one row, executed by warp 7 (lanes < 10 active in scan)
    auto scan_row = [&](int b, int buf) {
        float fused = 0.f;
        if (lane < 10) {
            const int h = lane;
            const float bias = s_bias[h];
            float mem = 0.f, acc = 0.f;
            #pragma unroll 6
            for (int t = 0; t < 90; ++t) {
                float inp = s_sn[buf][t][h] + bias;
                // reset from PREVIOUS mem, reset_mechanism='zero'
                float mem_new = (mem > 1.0f) ? 0.0f : fmaf(0.95f, mem, inp);
                if (mem_new > 1.0f) acc += s_wtime[t];   // spike
                mem = mem_new;
            }
            fused = acc + b_time[0];
        }
        // per-lane contribution to the two logits, reduce over warp
        float c0 = (lane < 10) ? fused * __ldg(w_out + lane)      : 0.f;
        float c1 = (lane < 10) ? fused * __ldg(w_out + 10 + lane) : 0.f;
        #pragma unroll
        for (int s = 16; s > 0; s >>= 1) {
            c0 += __shfl_xor_sync(0xffffffffu, c0, s);
            c1 += __shfl_xor_sync(0xffffffffu, c1, s);
        }
        if (lane == 0) {
            float o0 = c0 + b_out[0];
            float o1 = c1 + b_out[1];
            float m  = fmaxf(o0, o1);
            float e0 = __expf(o0 - m);
            float e1 = __expf(o1 - m);
            float inv = 1.0f / (e0 + e1);
            out[2 * b]     = e0 * inv;
            out[2 * b + 1] = e1 * inv;
        }
    };

    // ---- persistent loop: warps 0-6 produce sn, warp 7 scans previous row ----
    int iter = 0;
    int b;
    for (b = blockIdx.x; b < B; b += gridDim.x, ++iter) {
        const int buf = iter & 1;

        if (warp < 7) {
            // lane-offset base for this row (hoisted)
            const float4* xw = reinterpret_cast<const float4*>(x)
                             + (size_t)b * 90 * 256 + (size_t)warp * 256 + lane;
            for (int t = warp; t < 90; t += 7, xw += 7 * 256) {
                float acc[10];

                // ---- half 0: all 4 antennas, d-offset 0 ----
                {
                    float4 a0 = __ldcs(xw      );
                    float4 a1 = __ldcs(xw + 64 );
                    float4 a2 = __ldcs(xw + 128);
                    float4 a3 = __ldcs(xw + 192);
                    float4 f;
                    f.x = fmaf(a3.x, wa3, fmaf(a2.x, wa2, fmaf(a1.x, wa1, a0.x * wa0)));
                    f.y = fmaf(a3.y, wa3, fmaf(a2.y, wa2, fmaf(a1.y, wa1, a0.y * wa0)));
                    f.z = fmaf(a3.z, wa3, fmaf(a2.z, wa2, fmaf(a1.z, wa1, a0.z * wa0)));
                    f.w = fmaf(a3.w, wa3, fmaf(a2.w, wa2, fmaf(a1.w, wa1, a0.w * wa0)));
                    #pragma unroll
                    for (int h = 0; h < 10; ++h) {
                        float4 w = wl0[h * 64];
                        float r;
                        r = f.x * w.x;
                        r = fmaf(f.y, w.y, r);
                        r = fmaf(f.z, w.z, r);
                        r = fmaf(f.w, w.w, r);
                        acc[h] = r;
                    }
                }

                // ---- half 1: all 4 antennas, d-offset 32 (float4 units) ----
                {
                    float4 a0 = __ldcs(xw + 32 );
                    float4 a1 = __ldcs(xw + 96 );
                    float4 a2 = __ldcs(xw + 160);
                    float4 a3 = __ldcs(xw + 224);
                    float4 f;
                    f.x = fmaf(a3.x, wa3, fmaf(a2.x, wa2, fmaf(a1.x, wa1, a0.x * wa0)));
                    f.y = fmaf(a3.y, wa3, fmaf(a2.y, wa2, fmaf(a1.y, wa1, a0.y * wa0)));
                    f.z = fmaf(a3.z, wa3, fmaf(a2.z, wa2, fmaf(a1.z, wa1, a0.z * wa0)));
                    f.w = fmaf(a3.w, wa3, fmaf(a2.w, wa2, fmaf(a1.w, wa1, a0.w * wa0)));
                    #pragma unroll
                    for (int h = 0; h < 10; ++h) {
                        float4 w = wl1[h * 64];
                        float r = acc[h];
                        r = fmaf(f.x, w.x, r);
                        r = fmaf(f.y, w.y, r);
                        r = fmaf(f.z, w.z, r);
                        r = fmaf(f.w, w.w, r);
                        acc[h] = r;
                    }
                }

                // ---- log-packed warp reduction: 12 SHFL ----
                float v0 = pair_reduce(acc[0], acc[1], 16, lane);
                float v1 = pair_reduce(acc[2], acc[3], 16, lane);
                float v2 = pair_reduce(acc[4], acc[5], 16, lane);
                float v3 = pair_reduce(acc[6], acc[7], 16, lane);
                float v4 = pair_reduce(acc[8], acc[9], 16, lane);
                float u0 = pair_reduce(v0, v1, 8, lane);
                float u1 = pair_reduce(v2, v3, 8, lane);
                v4 += __shfl_xor_sync(0xffffffffu, v4, 8);
                float w0r = pair_reduce(u0, u1, 4, lane);
                v4 += __shfl_xor_sync(0xffffffffu, v4, 4);
                float z = pair_reduce(w0r, v4, 2, lane);
                z += __shfl_xor_sync(0xffffffffu, z, 1);

                if (writer) s_sn[buf][t][h_mine] = z;
            }
        } else {
            // warp 7: scan the previous row (produced last iteration)
            if (iter > 0) scan_row(b - gridDim.x, buf ^ 1);
        }
        __syncthreads();
    }

    // ---- epilogue: scan the final row ----
    if (iter > 0 && warp == 7) {
        scan_row(b - gridDim.x, (iter - 1) & 1);
    }
}

extern "C" void kernel_launch(void* const* d_in, const int* in_sizes, int n_in,
                              void* d_out, int out_size) {
    const float* x      = (const float*)d_in[0];
    const float* w_ant  = (const float*)d_in[1];
    const float* b_ant  = (const float*)d_in[2];
    const float* w_hid  = (const float*)d_in[3];
    const float* b_hid  = (const float*)d_in[4];
    const float* w_time = (const float*)d_in[5];
    const float* b_time = (const float*)d_in[6];
    const float* w_out  = (const float*)d_in[7];
    const float* b_out  = (const float*)d_in[8];
    float* out = (float*)d_out;

    const int B = in_sizes[0] / (90 * 4 * 256);   // 2048
    // capacity = 148 SMs * 6 CTAs = 888 slots; 3 rows/CTA -> grid 683, one wave
    const int rows_per = (B + 887) / 888;                 // 3 for B=2048
    int grid = (B + rows_per - 1) / rows_per;             // 683
    if (grid > B) grid = B;
    snn_fused_kernel<<<grid, THREADS>>>(x, w_ant, b_ant, w_hid, b_hid,
                                        w_time, b_time, w_out, b_out, out, B);
}